// round 15
// baseline (speedup 1.0000x reference)
#include <cuda_runtime.h>
#include <cuda_bf16.h>
#include <math.h>
#include <stdint.h>

#define TT 2048
#define HH 1024
#define II 1024
#define EE 16
#define KK 4
#define PP (TT*KK)
#define ALPHA 1.702f
#define LIMIT 7.0f
#define EPSV 1e-5f

// GEMM tiling: CTA 64M x 128N, K stage 64 (128B bf16 rows), 3-stage cp.async
// 128 threads = 4 warps (2m x 2n), warp tile 32x64.
#define KT 64
#define NK 16
#define AST (64*128)           // 8 KB
#define BST (128*128)          // 16 KB
#define STG (AST+BST)          // 24 KB
#define SMEM_NEED (3*STG)      // 72 KB -> 3 CTAs/SM

// ---------------- scratch ----------------------------------------------------
__device__ __nv_bfloat16 g_tnorm[(size_t)TT*HH];
__device__ __nv_bfloat16 g_w1b[(size_t)EE*2*II*HH];   // 64 MB
__device__ __nv_bfloat16 g_w2b[(size_t)EE*HH*II];     // 32 MB
__device__ int   g_cnt[EE];
__device__ int   g_base[EE];
__device__ int   g_slot_tok[PP];
__device__ int   g_pair_slot[PP];
__device__ int   g_topk_e[PP];
__device__ float g_topk_w[PP];
__device__ __nv_bfloat16 g_act[(size_t)PP*II];
__device__ float g_ypair[(size_t)PP*HH];

// ---------------- asm helpers ------------------------------------------------
__device__ __forceinline__ unsigned su32(const void* p) {
    return (unsigned)__cvta_generic_to_shared(p);
}
__device__ __forceinline__ void cp16(unsigned dst, const void* src, int sz) {
    asm volatile("cp.async.cg.shared.global [%0], [%1], 16, %2;\n"
                 :: "r"(dst), "l"(src), "r"(sz));
}
__device__ __forceinline__ void cp_commit() { asm volatile("cp.async.commit_group;"); }
template<int N> __device__ __forceinline__ void cp_waitN() {
    asm volatile("cp.async.wait_group %0;" :: "n"(N));
}
__device__ __forceinline__ void ldsm4(unsigned* r, unsigned addr) {
    asm volatile("ldmatrix.sync.aligned.m8n8.x4.shared.b16 {%0,%1,%2,%3}, [%4];"
                 : "=r"(r[0]), "=r"(r[1]), "=r"(r[2]), "=r"(r[3]) : "r"(addr));
}
__device__ __forceinline__ void mma_bf16(float* d, const unsigned* a, const unsigned* b) {
    asm volatile(
        "mma.sync.aligned.m16n8k16.row.col.f32.bf16.bf16.f32 "
        "{%0,%1,%2,%3},{%4,%5,%6,%7},{%8,%9},{%0,%1,%2,%3};"
        : "+f"(d[0]), "+f"(d[1]), "+f"(d[2]), "+f"(d[3])
        : "r"(a[0]), "r"(a[1]), "r"(a[2]), "r"(a[3]), "r"(b[0]), "r"(b[1]));
}
__device__ __forceinline__ unsigned pk_bf16x2(float lo, float hi) {
    __nv_bfloat162 v = __floats2bfloat162_rn(lo, hi);
    return *(unsigned*)&v;
}

// ---------------- weight converts fp32 -> bf16 (halved for overlap) ----------
__global__ __launch_bounds__(256) void k_cvt1(const float* __restrict__ w1, int ebase) {
    const size_t off = (size_t)ebase * 2 * II * HH / 4;
    size_t i = (size_t)blockIdx.x * 256 + threadIdx.x;
    float4 v = ((const float4*)w1)[off + i];
    ((uint2*)g_w1b)[off + i] = make_uint2(pk_bf16x2(v.x, v.y), pk_bf16x2(v.z, v.w));
}
__global__ __launch_bounds__(256) void k_cvt2(const float* __restrict__ w2) {
    const size_t N2 = (size_t)EE*HH*II/4;
    size_t i = (size_t)blockIdx.x * 256 + threadIdx.x;
    if (i < N2) {
        float4 v = ((const float4*)w2)[i];
        ((uint2*)g_w2b)[i] = make_uint2(pk_bf16x2(v.x, v.y), pk_bf16x2(v.z, v.w));
    }
}

// ---------------- kernel 1: rmsnorm + gate + top-4 + softmax -----------------
__global__ __launch_bounds__(256) void k_norm_gate(
    const float* __restrict__ x, const float* __restrict__ nscale,
    const float* __restrict__ gw, const float* __restrict__ gb)
{
    __shared__ float sg[256 * 17];
    __shared__ float sp[16][17];
    __shared__ float sred[8];
    __shared__ float logits[EE];

    int t = blockIdx.x;
    int tid = threadIdx.x;
    int wid = tid >> 5, lid = tid & 31;

    float4 xv = ((const float4*)(x + (size_t)t * HH))[tid];
    float ss = xv.x*xv.x + xv.y*xv.y + xv.z*xv.z + xv.w*xv.w;
    #pragma unroll
    for (int o = 16; o; o >>= 1) ss += __shfl_xor_sync(0xffffffffu, ss, o);

    if (lid == 0) sred[wid] = ss;
    __syncthreads();
    float tot = 0.f;
    #pragma unroll
    for (int w = 0; w < 8; w++) tot += sred[w];
    float rinv = rsqrtf(tot / (float)HH + EPSV);

    float4 sv = ((const float4*)nscale)[tid];
    float4 tn;
    tn.x = xv.x * rinv * sv.x;
    tn.y = xv.y * rinv * sv.y;
    tn.z = xv.z * rinv * sv.z;
    tn.w = xv.w * rinv * sv.w;
    ((uint2*)(g_tnorm + (size_t)t * HH))[tid] =
        make_uint2(pk_bf16x2(tn.x, tn.y), pk_bf16x2(tn.z, tn.w));

    int h0 = tid * 4;
    #pragma unroll
    for (int e = 0; e < EE; e++) {
        const float4 gv = *(const float4*)&gw[e * HH + h0];
        sg[tid * 17 + e] = tn.x*gv.x + tn.y*gv.y + tn.z*gv.z + tn.w*gv.w;
    }
    __syncthreads();

    {
        int e = tid & 15, g = tid >> 4;
        float part = 0.f;
        #pragma unroll
        for (int j = 0; j < 16; j++) part += sg[(g + 16*j) * 17 + e];
        sp[g][e] = part;
    }
    __syncthreads();
    if (tid < EE) {
        float v = gb[tid];
        #pragma unroll
        for (int g2 = 0; g2 < 16; g2++) v += sp[g2][tid];
        logits[tid] = v;
    }
    __syncthreads();

    if (tid == 0) {
        float l[EE];
        #pragma unroll
        for (int e = 0; e < EE; e++) l[e] = logits[e];
        float vals[KK]; int ids[KK];
        #pragma unroll
        for (int k = 0; k < KK; k++) {
            int bi = 0; float bv = l[0];
            #pragma unroll
            for (int e = 1; e < EE; e++) if (l[e] > bv) { bv = l[e]; bi = e; }
            vals[k] = bv; ids[k] = bi; l[bi] = -INFINITY;
        }
        float mx = vals[0];
        float wv[KK]; float s = 0.f;
        #pragma unroll
        for (int k = 0; k < KK; k++) { wv[k] = expf(vals[k] - mx); s += wv[k]; }
        float inv = 1.f / s;
        #pragma unroll
        for (int k = 0; k < KK; k++) {
            g_topk_e[t*KK + k] = ids[k];
            g_topk_w[t*KK + k] = wv[k] * inv;
        }
    }
}

// ---------------- kernel 2: fused count + prefix + routing (single block) ----
__global__ __launch_bounds__(1024) void k_sched() {
    __shared__ int scnt[EE];
    __shared__ int scur[EE];
    int tid = threadIdx.x;
    if (tid < EE) scnt[tid] = 0;
    __syncthreads();
    for (int p = tid; p < PP; p += 1024)
        atomicAdd(&scnt[g_topk_e[p]], 1);
    __syncthreads();
    if (tid == 0) {
        int s = 0;
        #pragma unroll
        for (int e = 0; e < EE; e++) {
            g_cnt[e] = scnt[e];
            g_base[e] = s; scur[e] = s; s += scnt[e];
        }
    }
    __syncthreads();
    for (int p = tid; p < PP; p += 1024) {
        int e = g_topk_e[p];
        int pos = atomicAdd(&scur[e], 1);
        g_slot_tok[pos] = p / KK;
        g_pair_slot[p] = pos;
    }
}

// ============================================================================
// bf16 HMMA GEMMs: CTA 64M x 128N x 64K, 4 warps (2m x 2n), warp tile 32x64.
// 6 ldsm.x4 per 16 mma (0.375 ldsm/mma, was 0.5). 3-stage cp.async ring,
// single __syncthreads per k-tile, 3 CTAs/SM. m-tiles fastest for L2 W-reuse.
// smem rows 128B, swizzle chunk ^= (row&7).
// ============================================================================

// A fill (128 thr): row ar = tid>>1, chunks acb..acb+3 (acb=(tid&1)*4)
__device__ __forceinline__ void fillA_sz(unsigned dstrow, const __nv_bfloat16* p,
                                         int ar, int acb, int sz) {
    #pragma unroll
    for (int c = 0; c < 4; c++) {
        int ch = acb + c;
        cp16(dstrow + ((ch ^ (ar & 7)) * 16), p + ch*8, sz);
    }
}
// B fill (128 thr): row = tid, all 8 chunks
__device__ __forceinline__ void fillB(unsigned dstrow, const __nv_bfloat16* p, int br) {
    #pragma unroll
    for (int c = 0; c < 8; c++)
        cp16(dstrow + ((c ^ (br & 7)) * 16), p + c*8, 16);
}

// one k16 step: warp tile 32M x 64N = 2 a-ldsm4, 4 b-ldsm4, 16 mma
__device__ __forceinline__ void do_ks(
    unsigned aBase, unsigned bBase, int ks, int wm, int wn, int lane,
    float acc[2][8][4])
{
    int q = lane >> 3, rr = lane & 7;
    unsigned a[2][4];
    #pragma unroll
    for (int mi = 0; mi < 2; mi++) {
        int row = wm*32 + mi*16 + (q & 1)*8 + rr;
        int ch  = 2*ks + (q >> 1);
        ldsm4(a[mi], aBase + row*128 + ((ch ^ (row & 7)) * 16));
    }
    unsigned b[8][2];
    #pragma unroll
    for (int p = 0; p < 4; p++) {
        int row = wn*64 + p*16 + (q >> 1)*8 + rr;
        int ch  = 2*ks + (q & 1);
        unsigned r4[4];
        ldsm4(r4, bBase + row*128 + ((ch ^ (row & 7)) * 16));
        b[2*p][0] = r4[0]; b[2*p][1] = r4[1];
        b[2*p+1][0] = r4[2]; b[2*p+1][1] = r4[3];
    }
    #pragma unroll
    for (int mi = 0; mi < 2; mi++)
        #pragma unroll
        for (int ni = 0; ni < 8; ni++)
            mma_bf16(acc[mi][ni], a[mi], b[ni]);
}

__device__ __forceinline__ void gemm_mainloop(
    char* sm, const __nv_bfloat16* arow, int asz,
    const __nv_bfloat16* brow, int tid, int wm, int wn, int lane,
    float acc[2][8][4])
{
    int ar = tid >> 1, acb = (tid & 1) * 4;
    unsigned aRow0 = su32(sm) + ar*128;
    unsigned bRow0 = su32(sm) + AST + tid*128;

    #pragma unroll
    for (int s = 0; s < 2; s++) {
        fillA_sz(aRow0 + s*STG, arow + s*KT, ar, acb, asz);
        fillB(bRow0 + s*STG, brow + s*KT, tid);
        cp_commit();
    }

    #pragma unroll 1
    for (int kt = 0; kt < NK; kt++) {
        if (kt + 1 < NK) cp_waitN<1>(); else cp_waitN<0>();
        __syncthreads();
        int s = kt % 3;
        unsigned aB = su32(sm) + s*STG;
        unsigned bB = aB + AST;
        do_ks(aB, bB, 0, wm, wn, lane, acc);
        do_ks(aB, bB, 1, wm, wn, lane, acc);
        if (kt + 2 < NK) {
            int sn = (kt + 2) % 3;
            fillA_sz(aRow0 + sn*STG, arow + (kt + 2)*KT, ar, acb, asz);
            fillB(bRow0 + sn*STG, brow + (kt + 2)*KT, tid);
        }
        do_ks(aB, bB, 2, wm, wn, lane, acc);
        do_ks(aB, bB, 3, wm, wn, lane, acc);
        cp_commit();
    }
}

// ---------------- GEMM1: h = tnorm @ W1^T, fused bias+swiglu -----------------
__global__ __launch_bounds__(128, 3) void k_gemm1(const float* __restrict__ b1, int ebase)
{
    extern __shared__ char sm[];
    int e = ebase + blockIdx.z;
    int cnt = g_cnt[e], m0 = blockIdx.x * 64;      // m fastest
    if (m0 >= cnt) return;
    int base = g_base[e], n0 = blockIdx.y * 128;   // n second

    int tid = threadIdx.x;
    int wid = tid >> 5, lane = tid & 31;
    int wm = wid & 1, wn = wid >> 1;
    int lr = lane >> 2, lc = lane & 3;

    int ar = tid >> 1;
    int mytok = (m0 + ar < cnt) ? g_slot_tok[base + m0 + ar] : -1;
    const __nv_bfloat16* arow = g_tnorm + (size_t)(mytok < 0 ? 0 : mytok) * HH;
    int asz = (mytok < 0) ? 0 : 16;
    const __nv_bfloat16* brow = g_w1b + ((size_t)e * 2 * II + n0 + tid) * HH;

    float acc[2][8][4];
    #pragma unroll
    for (int mi = 0; mi < 2; mi++)
        #pragma unroll
        for (int ni = 0; ni < 8; ni++)
            #pragma unroll
            for (int j = 0; j < 4; j++) acc[mi][ni][j] = 0.f;

    gemm_mainloop(sm, arow, asz, brow, tid, wm, wn, lane, acc);

    #pragma unroll
    for (int ni = 0; ni < 8; ni++) {
        int ng = n0 + wn*64 + ni*8 + 2*lc;
        float be = b1[e * 2 * II + ng];
        float bo = b1[e * 2 * II + ng + 1];
        int icol = ng >> 1;
        #pragma unroll
        for (int mi = 0; mi < 2; mi++) {
            int mrow = m0 + wm*32 + mi*16 + lr;
            #pragma unroll
            for (int half = 0; half < 2; half++) {
                int rr = mrow + half * 8;
                if (rr >= cnt) continue;
                float he = acc[mi][ni][2*half]     + be;
                float ho = acc[mi][ni][2*half + 1] + bo;
                float glu = fminf(he, LIMIT);
                float lin = fminf(fmaxf(ho, -LIMIT), LIMIT);
                float sgm = 1.f / (1.f + expf(-ALPHA * glu));
                g_act[(size_t)(base + rr) * II + icol] = __float2bfloat16(glu * sgm * (lin + 1.f));
            }
        }
    }
}

// ---------------- GEMM2: ypair = act @ W2^T ----------------------------------
__global__ __launch_bounds__(128, 3) void k_gemm2(int ebase)
{
    extern __shared__ char sm[];
    int e = ebase + blockIdx.z;
    int cnt = g_cnt[e], m0 = blockIdx.x * 64;      // m fastest
    if (m0 >= cnt) return;
    int base = g_base[e], n0 = blockIdx.y * 128;

    int tid = threadIdx.x;
    int wid = tid >> 5, lane = tid & 31;
    int wm = wid & 1, wn = wid >> 1;
    int lr = lane >> 2, lc = lane & 3;

    int ar = tid >> 1;
    bool av = (m0 + ar) < cnt;
    const __nv_bfloat16* arow = g_act + (size_t)(base + (av ? m0 + ar : 0)) * II;
    int asz = av ? 16 : 0;
    const __nv_bfloat16* brow = g_w2b + ((size_t)e * HH + n0 + tid) * II;

    float acc[2][8][4];
    #pragma unroll
    for (int mi = 0; mi < 2; mi++)
        #pragma unroll
        for (int ni = 0; ni < 8; ni++)
            #pragma unroll
            for (int j = 0; j < 4; j++) acc[mi][ni][j] = 0.f;

    gemm_mainloop(sm, arow, asz, brow, tid, wm, wn, lane, acc);

    #pragma unroll
    for (int ni = 0; ni < 8; ni++) {
        int ng = n0 + wn*64 + ni*8 + 2*lc;
        #pragma unroll
        for (int mi = 0; mi < 2; mi++) {
            int mrow = m0 + wm*32 + mi*16 + lr;
            #pragma unroll
            for (int half = 0; half < 2; half++) {
                int rr = mrow + half * 8;
                if (rr >= cnt) continue;
                *(float2*)&g_ypair[(size_t)(base + rr) * HH + ng] =
                    make_float2(acc[mi][ni][2*half], acc[mi][ni][2*half + 1]);
            }
        }
    }
}

// ---------------- final: out = x + sum_k w_k * (ypair + b2[e]) ---------------
__global__ __launch_bounds__(256) void k_final(
    const float* __restrict__ x, const float* __restrict__ b2, float* __restrict__ out)
{
    int t = blockIdx.x;
    int tid = threadIdx.x;
    int h0 = tid * 4;
    float4 r = ((const float4*)(x + (size_t)t * HH))[tid];
    #pragma unroll
    for (int k = 0; k < KK; k++) {
        int e   = g_topk_e[t*KK + k];
        float w = g_topk_w[t*KK + k];
        int s   = g_pair_slot[t*KK + k];
        float4 y  = *(const float4*)&g_ypair[(size_t)s * HH + h0];
        float4 bv = *(const float4*)&b2[e * HH + h0];
        r.x += w * (y.x + bv.x);
        r.y += w * (y.y + bv.y);
        r.z += w * (y.z + bv.z);
        r.w += w * (y.w + bv.w);
    }
    ((float4*)(out + (size_t)t * HH))[tid] = r;
}

// ---------------- launcher ---------------------------------------------------
extern "C" void kernel_launch(void* const* d_in, const int* in_sizes, int n_in,
                              void* d_out, int out_size)
{
    (void)in_sizes; (void)n_in; (void)out_size;
    const float* x      = (const float*)d_in[0];
    const float* nscale = (const float*)d_in[1];
    const float* gw     = (const float*)d_in[2];
    const float* gb     = (const float*)d_in[3];
    const float* w1     = (const float*)d_in[4];
    const float* b1     = (const float*)d_in[5];
    const float* w2     = (const float*)d_in[6];
    const float* b2     = (const float*)d_in[7];
    float* out = (float*)d_out;

    static cudaStream_t s2 = nullptr;
    static cudaEvent_t evFork = nullptr, evA = nullptr, evC2 = nullptr,
                       evRoute = nullptr, evDoneB = nullptr;
    static bool init_done = false;
    if (!init_done) {
        cudaFuncSetAttribute(k_gemm1, cudaFuncAttributeMaxDynamicSharedMemorySize, SMEM_NEED);
        cudaFuncSetAttribute(k_gemm2, cudaFuncAttributeMaxDynamicSharedMemorySize, SMEM_NEED);
        cudaStreamCreateWithFlags(&s2, cudaStreamNonBlocking);
        cudaEventCreateWithFlags(&evFork, cudaEventDisableTiming);
        cudaEventCreateWithFlags(&evA, cudaEventDisableTiming);
        cudaEventCreateWithFlags(&evC2, cudaEventDisableTiming);
        cudaEventCreateWithFlags(&evRoute, cudaEventDisableTiming);
        cudaEventCreateWithFlags(&evDoneB, cudaEventDisableTiming);
        init_done = true;
    }

    const unsigned CVT1_HALF_BLOCKS = (unsigned)(8ull * 2 * II * HH / 4 / 256);
    const unsigned CVT2_BLOCKS      = (unsigned)((size_t)EE * HH * II / 4 / 256);

    // fork immediately: cvt chain on s2
    cudaEventRecord(evFork, 0);
    cudaStreamWaitEvent(s2, evFork, 0);
    k_cvt1<<<CVT1_HALF_BLOCKS, 256, 0, s2>>>(w1, 0);
    cudaEventRecord(evA, s2);                          // w1 experts 0-7 ready
    k_cvt1<<<CVT1_HALF_BLOCKS, 256, 0, s2>>>(w1, 8);
    k_cvt2<<<CVT2_BLOCKS, 256, 0, s2>>>(w2);
    cudaEventRecord(evC2, s2);                         // all weights ready

    // routing chain on stream 0
    k_norm_gate<<<TT, 256>>>(x, nscale, gw, gb);
    k_sched<<<1, 1024>>>();
    cudaEventRecord(evRoute, 0);

    dim3 g1(32, 16, 8);    // m-tiles fastest, n-tiles (2I/128), 8 experts/half
    dim3 g2(32, 8, 8);     // m-tiles fastest, n-tiles (H/128),  8 experts/half

    // half B on s2
    cudaStreamWaitEvent(s2, evRoute, 0);
    k_gemm1<<<g1, 128, SMEM_NEED, s2>>>(b1, 8);
    k_gemm2<<<g2, 128, SMEM_NEED, s2>>>(8);
    cudaEventRecord(evDoneB, s2);

    // half A on stream 0
    cudaStreamWaitEvent(0, evA, 0);
    k_gemm1<<<g1, 128, SMEM_NEED>>>(b1, 0);
    cudaStreamWaitEvent(0, evC2, 0);
    k_gemm2<<<g2, 128, SMEM_NEED>>>(0);

    // join + final combine
    cudaStreamWaitEvent(0, evDoneB, 0);
    k_final<<<TT, 256>>>(x, b2, out);
}

// round 16
// speedup vs baseline: 1.3761x; 1.3761x over previous
#include <cuda_runtime.h>
#include <cuda_bf16.h>
#include <math.h>
#include <stdint.h>

#define TT 2048
#define HH 1024
#define II 1024
#define EE 16
#define KK 4
#define PP (TT*KK)
#define ALPHA 1.702f
#define LIMIT 7.0f
#define EPSV 1e-5f

// GEMM tiling: CTA 64M x 128N, K stage 64 (128B bf16 rows), 3-stage cp.async
#define KT 64
#define NK 16
#define AST (64*128)           // 8 KB
#define BST (128*128)          // 16 KB
#define STG (AST+BST)          // 24 KB
#define SMEM_NEED (3*STG)      // 72 KB -> 3 CTAs/SM

// ---------------- scratch ----------------------------------------------------
__device__ __nv_bfloat16 g_tnorm[(size_t)TT*HH];
__device__ __nv_bfloat16 g_w1b[(size_t)EE*2*II*HH];   // 64 MB
__device__ __nv_bfloat16 g_w2b[(size_t)EE*HH*II];     // 32 MB
__device__ int   g_cnt[EE];
__device__ int   g_base[EE];
__device__ int   g_slot_tok[PP];
__device__ int   g_pair_slot[PP];
__device__ int   g_topk_e[PP];
__device__ float g_topk_w[PP];
__device__ __nv_bfloat16 g_act[(size_t)PP*II];
__device__ float g_ypair[(size_t)PP*HH];

// ---------------- asm helpers ------------------------------------------------
__device__ __forceinline__ unsigned su32(const void* p) {
    return (unsigned)__cvta_generic_to_shared(p);
}
__device__ __forceinline__ void cp16(unsigned dst, const void* src, int sz) {
    asm volatile("cp.async.cg.shared.global [%0], [%1], 16, %2;\n"
                 :: "r"(dst), "l"(src), "r"(sz));
}
__device__ __forceinline__ void cp_commit() { asm volatile("cp.async.commit_group;"); }
template<int N> __device__ __forceinline__ void cp_waitN() {
    asm volatile("cp.async.wait_group %0;" :: "n"(N));
}
__device__ __forceinline__ void ldsm4(unsigned* r, unsigned addr) {
    asm volatile("ldmatrix.sync.aligned.m8n8.x4.shared.b16 {%0,%1,%2,%3}, [%4];"
                 : "=r"(r[0]), "=r"(r[1]), "=r"(r[2]), "=r"(r[3]) : "r"(addr));
}
__device__ __forceinline__ void mma_bf16(float* d, const unsigned* a, const unsigned* b) {
    asm volatile(
        "mma.sync.aligned.m16n8k16.row.col.f32.bf16.bf16.f32 "
        "{%0,%1,%2,%3},{%4,%5,%6,%7},{%8,%9},{%0,%1,%2,%3};"
        : "+f"(d[0]), "+f"(d[1]), "+f"(d[2]), "+f"(d[3])
        : "r"(a[0]), "r"(a[1]), "r"(a[2]), "r"(a[3]), "r"(b[0]), "r"(b[1]));
}
__device__ __forceinline__ unsigned pk_bf16x2(float lo, float hi) {
    __nv_bfloat162 v = __floats2bfloat162_rn(lo, hi);
    return *(unsigned*)&v;
}

// ---------------- weight converts fp32 -> bf16 (halved for overlap) ----------
__global__ __launch_bounds__(256) void k_cvt1(const float* __restrict__ w1, int ebase) {
    const size_t off = (size_t)ebase * 2 * II * HH / 4;
    size_t i = (size_t)blockIdx.x * 256 + threadIdx.x;
    float4 v = ((const float4*)w1)[off + i];
    ((uint2*)g_w1b)[off + i] = make_uint2(pk_bf16x2(v.x, v.y), pk_bf16x2(v.z, v.w));
}
__global__ __launch_bounds__(256) void k_cvt2(const float* __restrict__ w2) {
    const size_t N2 = (size_t)EE*HH*II/4;
    size_t i = (size_t)blockIdx.x * 256 + threadIdx.x;
    if (i < N2) {
        float4 v = ((const float4*)w2)[i];
        ((uint2*)g_w2b)[i] = make_uint2(pk_bf16x2(v.x, v.y), pk_bf16x2(v.z, v.w));
    }
}

// ---------------- kernel 1: rmsnorm + gate + top-4 + softmax -----------------
// gate reduction via padded smem transpose
__global__ __launch_bounds__(256) void k_norm_gate(
    const float* __restrict__ x, const float* __restrict__ nscale,
    const float* __restrict__ gw, const float* __restrict__ gb)
{
    __shared__ float sg[256 * 17];     // padded: row stride 17 floats
    __shared__ float sp[16][17];
    __shared__ float sred[8];
    __shared__ float logits[EE];

    int t = blockIdx.x;
    int tid = threadIdx.x;
    int wid = tid >> 5, lid = tid & 31;

    float4 xv = ((const float4*)(x + (size_t)t * HH))[tid];
    float ss = xv.x*xv.x + xv.y*xv.y + xv.z*xv.z + xv.w*xv.w;
    #pragma unroll
    for (int o = 16; o; o >>= 1) ss += __shfl_xor_sync(0xffffffffu, ss, o);

    if (lid == 0) sred[wid] = ss;
    __syncthreads();
    float tot = 0.f;
    #pragma unroll
    for (int w = 0; w < 8; w++) tot += sred[w];
    float rinv = rsqrtf(tot / (float)HH + EPSV);

    float4 sv = ((const float4*)nscale)[tid];
    float4 tn;
    tn.x = xv.x * rinv * sv.x;
    tn.y = xv.y * rinv * sv.y;
    tn.z = xv.z * rinv * sv.z;
    tn.w = xv.w * rinv * sv.w;
    ((uint2*)(g_tnorm + (size_t)t * HH))[tid] =
        make_uint2(pk_bf16x2(tn.x, tn.y), pk_bf16x2(tn.z, tn.w));

    // per-thread partial gate dots (exact fp32)
    int h0 = tid * 4;
    #pragma unroll
    for (int e = 0; e < EE; e++) {
        const float4 gv = *(const float4*)&gw[e * HH + h0];
        sg[tid * 17 + e] = tn.x*gv.x + tn.y*gv.y + tn.z*gv.z + tn.w*gv.w;
    }
    __syncthreads();

    // strided column reduction: thread handles expert e = tid&15, group g = tid>>4
    {
        int e = tid & 15, g = tid >> 4;
        float part = 0.f;
        #pragma unroll
        for (int j = 0; j < 16; j++) part += sg[(g + 16*j) * 17 + e];
        sp[g][e] = part;
    }
    __syncthreads();
    if (tid < EE) {
        float v = gb[tid];
        #pragma unroll
        for (int g2 = 0; g2 < 16; g2++) v += sp[g2][tid];
        logits[tid] = v;
    }
    __syncthreads();

    if (tid == 0) {
        float l[EE];
        #pragma unroll
        for (int e = 0; e < EE; e++) l[e] = logits[e];
        float vals[KK]; int ids[KK];
        #pragma unroll
        for (int k = 0; k < KK; k++) {
            int bi = 0; float bv = l[0];
            #pragma unroll
            for (int e = 1; e < EE; e++) if (l[e] > bv) { bv = l[e]; bi = e; }
            vals[k] = bv; ids[k] = bi; l[bi] = -INFINITY;
        }
        float mx = vals[0];
        float wv[KK]; float s = 0.f;
        #pragma unroll
        for (int k = 0; k < KK; k++) { wv[k] = expf(vals[k] - mx); s += wv[k]; }
        float inv = 1.f / s;
        #pragma unroll
        for (int k = 0; k < KK; k++) {
            g_topk_e[t*KK + k] = ids[k];
            g_topk_w[t*KK + k] = wv[k] * inv;
        }
    }
}

// ---------------- kernel 2: fused count + prefix + routing (single block) ----
__global__ __launch_bounds__(1024) void k_sched() {
    __shared__ int scnt[EE];
    __shared__ int scur[EE];
    int tid = threadIdx.x;
    if (tid < EE) scnt[tid] = 0;
    __syncthreads();
    for (int p = tid; p < PP; p += 1024)
        atomicAdd(&scnt[g_topk_e[p]], 1);
    __syncthreads();
    if (tid == 0) {
        int s = 0;
        #pragma unroll
        for (int e = 0; e < EE; e++) {
            g_cnt[e] = scnt[e];
            g_base[e] = s; scur[e] = s; s += scnt[e];
        }
    }
    __syncthreads();
    for (int p = tid; p < PP; p += 1024) {
        int e = g_topk_e[p];
        int pos = atomicAdd(&scur[e], 1);
        g_slot_tok[pos] = p / KK;
        g_pair_slot[p] = pos;
    }
}

// ============================================================================
// bf16 HMMA GEMMs: CTA 64M x 128N x 64K, 8 warps (2m x 4n), warp tile 32x32.
// 3-stage cp.async ring, single __syncthreads per k-tile, 3 CTAs/SM
// (6 warps/SMSP — the measured optimum for the compat-HMMA path).
// Grid raster: m-tiles fastest for weight-tile L2 reuse.
// smem rows 128B, swizzle chunk ^= (row&7).
// ============================================================================

__device__ __forceinline__ void fillA_sz(unsigned dstrow, const __nv_bfloat16* p,
                                         int ar, int acb, int sz) {
    #pragma unroll
    for (int c = 0; c < 2; c++) {
        int ch = acb + c;
        cp16(dstrow + ((ch ^ (ar & 7)) * 16), p + ch*8, sz);
    }
}
__device__ __forceinline__ void fillB(unsigned dstrow, const __nv_bfloat16* p,
                                      int br, int bcb) {
    #pragma unroll
    for (int c = 0; c < 4; c++) {
        int ch = bcb + c;
        cp16(dstrow + ((ch ^ (br & 7)) * 16), p + ch*8, 16);
    }
}

// one k16 step: warp tile 32M x 32N = 2 a-frags, 4 b-frags, 8 mma
__device__ __forceinline__ void do_ks(
    unsigned aBase, unsigned bBase, int ks, int wm, int wn, int lane,
    float acc[2][4][4])
{
    int q = lane >> 3, rr = lane & 7;
    unsigned a[2][4];
    #pragma unroll
    for (int mi = 0; mi < 2; mi++) {
        int row = wm*32 + mi*16 + (q & 1)*8 + rr;
        int ch  = 2*ks + (q >> 1);
        ldsm4(a[mi], aBase + row*128 + ((ch ^ (row & 7)) * 16));
    }
    unsigned b[4][2];
    #pragma unroll
    for (int p = 0; p < 2; p++) {
        int row = wn*32 + p*16 + (q >> 1)*8 + rr;
        int ch  = 2*ks + (q & 1);
        unsigned r4[4];
        ldsm4(r4, bBase + row*128 + ((ch ^ (row & 7)) * 16));
        b[2*p][0] = r4[0]; b[2*p][1] = r4[1];
        b[2*p+1][0] = r4[2]; b[2*p+1][1] = r4[3];
    }
    #pragma unroll
    for (int mi = 0; mi < 2; mi++)
        #pragma unroll
        for (int ni = 0; ni < 4; ni++)
            mma_bf16(acc[mi][ni], a[mi], b[ni]);
}

__device__ __forceinline__ void gemm_mainloop(
    char* sm, const __nv_bfloat16* arow, int asz,
    const __nv_bfloat16* brow, int tid, int wm, int wn, int lane,
    float acc[2][4][4])
{
    int ar = tid >> 2, acb = (tid & 3) * 2;
    int br = tid >> 1, bcb = (tid & 1) * 4;
    unsigned aRow0 = su32(sm) + ar*128;
    unsigned bRow0 = su32(sm) + AST + br*128;

    #pragma unroll
    for (int s = 0; s < 2; s++) {
        fillA_sz(aRow0 + s*STG, arow + s*KT, ar, acb, asz);
        fillB(bRow0 + s*STG, brow + s*KT, br, bcb);
        cp_commit();
    }

    #pragma unroll 1
    for (int kt = 0; kt < NK; kt++) {
        if (kt + 1 < NK) cp_waitN<1>(); else cp_waitN<0>();
        __syncthreads();
        int s = kt % 3;
        unsigned aB = su32(sm) + s*STG;
        unsigned bB = aB + AST;
        do_ks(aB, bB, 0, wm, wn, lane, acc);
        do_ks(aB, bB, 1, wm, wn, lane, acc);
        if (kt + 2 < NK) {
            int sn = (kt + 2) % 3;
            fillA_sz(aRow0 + sn*STG, arow + (kt + 2)*KT, ar, acb, asz);
            fillB(bRow0 + sn*STG, brow + (kt + 2)*KT, br, bcb);
        }
        do_ks(aB, bB, 2, wm, wn, lane, acc);
        do_ks(aB, bB, 3, wm, wn, lane, acc);
        cp_commit();
    }
}

// ---------------- GEMM1: h = tnorm @ W1^T, fused bias+swiglu -----------------
__global__ __launch_bounds__(256, 3) void k_gemm1(const float* __restrict__ b1, int ebase)
{
    extern __shared__ char sm[];
    int e = ebase + blockIdx.z;
    int cnt = g_cnt[e], m0 = blockIdx.x * 64;      // m fastest
    if (m0 >= cnt) return;
    int base = g_base[e], n0 = blockIdx.y * 128;   // n second

    int tid = threadIdx.x;
    int wid = tid >> 5, lane = tid & 31;
    int wm = wid & 1, wn = wid >> 1;
    int lr = lane >> 2, lc = lane & 3;

    int ar = tid >> 2;
    int mytok = (m0 + ar < cnt) ? g_slot_tok[base + m0 + ar] : -1;
    const __nv_bfloat16* arow = g_tnorm + (size_t)(mytok < 0 ? 0 : mytok) * HH;
    int asz = (mytok < 0) ? 0 : 16;
    const __nv_bfloat16* brow = g_w1b + ((size_t)e * 2 * II + n0 + (tid >> 1)) * HH;

    float acc[2][4][4];
    #pragma unroll
    for (int mi = 0; mi < 2; mi++)
        #pragma unroll
        for (int ni = 0; ni < 4; ni++)
            #pragma unroll
            for (int j = 0; j < 4; j++) acc[mi][ni][j] = 0.f;

    gemm_mainloop(sm, arow, asz, brow, tid, wm, wn, lane, acc);

    #pragma unroll
    for (int ni = 0; ni < 4; ni++) {
        int ng = n0 + wn*32 + ni*8 + 2*lc;
        float be = b1[e * 2 * II + ng];
        float bo = b1[e * 2 * II + ng + 1];
        int icol = ng >> 1;
        #pragma unroll
        for (int mi = 0; mi < 2; mi++) {
            int mrow = m0 + wm*32 + mi*16 + lr;
            #pragma unroll
            for (int half = 0; half < 2; half++) {
                int rr = mrow + half * 8;
                if (rr >= cnt) continue;
                float he = acc[mi][ni][2*half]     + be;
                float ho = acc[mi][ni][2*half + 1] + bo;
                float glu = fminf(he, LIMIT);
                float lin = fminf(fmaxf(ho, -LIMIT), LIMIT);
                float sgm = 1.f / (1.f + expf(-ALPHA * glu));
                g_act[(size_t)(base + rr) * II + icol] = __float2bfloat16(glu * sgm * (lin + 1.f));
            }
        }
    }
}

// ---------------- GEMM2: ypair = act @ W2^T ----------------------------------
__global__ __launch_bounds__(256, 3) void k_gemm2(int ebase)
{
    extern __shared__ char sm[];
    int e = ebase + blockIdx.z;
    int cnt = g_cnt[e], m0 = blockIdx.x * 64;      // m fastest
    if (m0 >= cnt) return;
    int base = g_base[e], n0 = blockIdx.y * 128;

    int tid = threadIdx.x;
    int wid = tid >> 5, lane = tid & 31;
    int wm = wid & 1, wn = wid >> 1;
    int lr = lane >> 2, lc = lane & 3;

    int ar = tid >> 2;
    bool av = (m0 + ar) < cnt;
    const __nv_bfloat16* arow = g_act + (size_t)(base + (av ? m0 + ar : 0)) * II;
    int asz = av ? 16 : 0;
    const __nv_bfloat16* brow = g_w2b + ((size_t)e * HH + n0 + (tid >> 1)) * II;

    float acc[2][4][4];
    #pragma unroll
    for (int mi = 0; mi < 2; mi++)
        #pragma unroll
        for (int ni = 0; ni < 4; ni++)
            #pragma unroll
            for (int j = 0; j < 4; j++) acc[mi][ni][j] = 0.f;

    gemm_mainloop(sm, arow, asz, brow, tid, wm, wn, lane, acc);

    #pragma unroll
    for (int ni = 0; ni < 4; ni++) {
        int ng = n0 + wn*32 + ni*8 + 2*lc;
        #pragma unroll
        for (int mi = 0; mi < 2; mi++) {
            int mrow = m0 + wm*32 + mi*16 + lr;
            #pragma unroll
            for (int half = 0; half < 2; half++) {
                int rr = mrow + half * 8;
                if (rr >= cnt) continue;
                *(float2*)&g_ypair[(size_t)(base + rr) * HH + ng] =
                    make_float2(acc[mi][ni][2*half], acc[mi][ni][2*half + 1]);
            }
        }
    }
}

// ---------------- final: out = x + sum_k w_k * (ypair + b2[e]) ---------------
__global__ __launch_bounds__(256) void k_final(
    const float* __restrict__ x, const float* __restrict__ b2, float* __restrict__ out)
{
    int t = blockIdx.x;
    int tid = threadIdx.x;
    int h0 = tid * 4;
    float4 r = ((const float4*)(x + (size_t)t * HH))[tid];
    #pragma unroll
    for (int k = 0; k < KK; k++) {
        int e   = g_topk_e[t*KK + k];
        float w = g_topk_w[t*KK + k];
        int s   = g_pair_slot[t*KK + k];
        float4 y  = *(const float4*)&g_ypair[(size_t)s * HH + h0];
        float4 bv = *(const float4*)&b2[e * HH + h0];
        r.x += w * (y.x + bv.x);
        r.y += w * (y.y + bv.y);
        r.z += w * (y.z + bv.z);
        r.w += w * (y.w + bv.w);
    }
    ((float4*)(out + (size_t)t * HH))[tid] = r;
}

// ---------------- launcher ---------------------------------------------------
extern "C" void kernel_launch(void* const* d_in, const int* in_sizes, int n_in,
                              void* d_out, int out_size)
{
    (void)in_sizes; (void)n_in; (void)out_size;
    const float* x      = (const float*)d_in[0];
    const float* nscale = (const float*)d_in[1];
    const float* gw     = (const float*)d_in[2];
    const float* gb     = (const float*)d_in[3];
    const float* w1     = (const float*)d_in[4];
    const float* b1     = (const float*)d_in[5];
    const float* w2     = (const float*)d_in[6];
    const float* b2     = (const float*)d_in[7];
    float* out = (float*)d_out;

    static cudaStream_t s2 = nullptr;
    static cudaEvent_t evFork = nullptr, evA = nullptr, evC2 = nullptr,
                       evRoute = nullptr, evDoneB = nullptr;
    static bool init_done = false;
    if (!init_done) {
        cudaFuncSetAttribute(k_gemm1, cudaFuncAttributeMaxDynamicSharedMemorySize, SMEM_NEED);
        cudaFuncSetAttribute(k_gemm2, cudaFuncAttributeMaxDynamicSharedMemorySize, SMEM_NEED);
        cudaStreamCreateWithFlags(&s2, cudaStreamNonBlocking);
        cudaEventCreateWithFlags(&evFork, cudaEventDisableTiming);
        cudaEventCreateWithFlags(&evA, cudaEventDisableTiming);
        cudaEventCreateWithFlags(&evC2, cudaEventDisableTiming);
        cudaEventCreateWithFlags(&evRoute, cudaEventDisableTiming);
        cudaEventCreateWithFlags(&evDoneB, cudaEventDisableTiming);
        init_done = true;
    }

    const unsigned CVT1_HALF_BLOCKS = (unsigned)(8ull * 2 * II * HH / 4 / 256);
    const unsigned CVT2_BLOCKS      = (unsigned)((size_t)EE * HH * II / 4 / 256);

    // fork immediately: cvt chain on s2
    cudaEventRecord(evFork, 0);
    cudaStreamWaitEvent(s2, evFork, 0);
    k_cvt1<<<CVT1_HALF_BLOCKS, 256, 0, s2>>>(w1, 0);
    cudaEventRecord(evA, s2);                          // w1 experts 0-7 ready
    k_cvt1<<<CVT1_HALF_BLOCKS, 256, 0, s2>>>(w1, 8);
    k_cvt2<<<CVT2_BLOCKS, 256, 0, s2>>>(w2);
    cudaEventRecord(evC2, s2);                         // all weights ready

    // routing chain on stream 0
    k_norm_gate<<<TT, 256>>>(x, nscale, gw, gb);
    k_sched<<<1, 1024>>>();
    cudaEventRecord(evRoute, 0);

    dim3 g1(32, 16, 8);    // m-tiles fastest, n-tiles (2I/128), 8 experts/half
    dim3 g2(32, 8, 8);     // m-tiles fastest, n-tiles (H/128),  8 experts/half

    // half B on s2
    cudaStreamWaitEvent(s2, evRoute, 0);
    k_gemm1<<<g1, 256, SMEM_NEED, s2>>>(b1, 8);
    k_gemm2<<<g2, 256, SMEM_NEED, s2>>>(8);
    cudaEventRecord(evDoneB, s2);

    // half A on stream 0
    cudaStreamWaitEvent(0, evA, 0);
    k_gemm1<<<g1, 256, SMEM_NEED>>>(b1, 0);
    cudaStreamWaitEvent(0, evC2, 0);
    k_gemm2<<<g2, 256, SMEM_NEED>>>(0);

    // join + final combine
    cudaStreamWaitEvent(0, evDoneB, 0);
    k_final<<<TT, 256>>>(x, b2, out);
}